// round 3
// baseline (speedup 1.0000x reference)
#include <cuda_runtime.h>

// Problem constants (fixed shapes from the reference)
#define N_NODES   100000
#define NFEATS    256
#define HIDDEN    128
#define NCLASS    64
#define BATCH     1024
#define K0        25
#define K1        10
#define NHIST     5
#define ROWS_TOTAL (BATCH + BATCH * K1)   // 11264 layer0 rows
#define RPB        16                      // rows per block (pairs of 8)
#define NBLK       (ROWS_TOTAL / RPB)      // 704 blocks

// Scratch: layer0 outputs. rows [0,1024) = h1, rows [1024,11264) = neigh_original.
__device__ float g_L0[(size_t)ROWS_TOTAL * HIDDEN];

// ---- packed f32x2 helpers (Blackwell FFMA2; ptxas never emits these from C++) ----
__device__ __forceinline__ unsigned long long pack2(float lo, float hi) {
    unsigned long long r;
    asm("mov.b64 %0, {%1, %2};" : "=l"(r) : "f"(lo), "f"(hi));
    return r;
}
__device__ __forceinline__ void unpack2(unsigned long long v, float& lo, float& hi) {
    asm("mov.b64 {%0, %1}, %2;" : "=f"(lo), "=f"(hi) : "l"(v));
}
__device__ __forceinline__ void fma2(unsigned long long& d, unsigned long long a,
                                     unsigned long long b) {
    asm("fma.rn.f32x2 %0, %1, %2, %0;" : "+l"(d) : "l"(a), "l"(b));
}

// ============================================================================
// Kernel 1: fused gather-mean + [512]x[512,128] GEMV + bias + ReLU
// for all 11264 layer0 rows. 128 threads, 16 rows per block.
//
// smem layout: xs[p][k] = float2( x[row 2p][k], x[row 2p+1][k] ), k in [0,512)
//   k <  256 : self features
//   k >= 256 : mean of 25 gathered neighbor features
// Phase 2 reads ulonglong2 at (p, k even) -> two packed x-operands, multiplies
// by broadcast-packed weight columns with fma.rn.f32x2 (2 FMA / instr).
// ============================================================================
__global__ __launch_bounds__(128)
void layer0_kernel(const float* __restrict__ feats,
                   const float* __restrict__ W0,
                   const float* __restrict__ b0,
                   const int*   __restrict__ nodes,
                   const int*   __restrict__ neighs0,
                   const int*   __restrict__ neighs1,
                   const int*   __restrict__ neighs0_nb)
{
    __shared__ __align__(16) float2 xs[RPB / 2][2 * NFEATS];  // 32 KB

    const int t    = threadIdx.x;           // feature column pair: cols 2t, 2t+1
    const int row0 = blockIdx.x * RPB;
    const float2* f2 = (const float2*)feats;

    // ---------------- Phase 1: gather + mean ----------------
    #pragma unroll 1
    for (int r = 0; r < RPB; r++) {
        const int row = row0 + r;
        int self;
        const int* nb;
        if (row < BATCH) {                  // root rows: nodes / neighs0
            self = nodes[row];
            nb   = neighs0 + row * K0;
        } else {                            // neighbor rows: neighs1 / neighs0_nb
            const int j = row - BATCH;
            self = neighs1[j];
            nb   = neighs0_nb + j * K0;
        }
        const float2 sv = f2[(size_t)self * (NFEATS / 2) + t];
        float sx = 0.f, sy = 0.f;
        #pragma unroll
        for (int k = 0; k < K0; k++) {
            const int n = nb[k];
            const float2 v = f2[(size_t)n * (NFEATS / 2) + t];
            sx += v.x; sy += v.y;
        }
        sx *= (1.f / K0);
        sy *= (1.f / K0);

        // interleaved store: float index = k*2 + (r&1) within pair p = r>>1
        float* base = (float*)&xs[r >> 1][0];
        const int lane = r & 1;
        base[4 * t + lane]             = sv.x;   // k = 2t
        base[4 * t + 2 + lane]         = sv.y;   // k = 2t+1
        base[2 * NFEATS + 4 * t + lane]     = sx; // k = 256+2t
        base[2 * NFEATS + 4 * t + 2 + lane] = sy; // k = 256+2t+1
    }
    __syncthreads();

    // ---------------- Phase 2: GEMV with packed FFMA2 ----------------
    unsigned long long acc[RPB / 2];
    #pragma unroll
    for (int p = 0; p < RPB / 2; p++) acc[p] = 0ull;  // bit pattern (0.f, 0.f)

    #pragma unroll 2
    for (int k = 0; k < 2 * NFEATS; k += 2) {
        const float w0 = W0[(size_t)k * HIDDEN + t];          // coalesced column read
        const float w1 = W0[(size_t)k * HIDDEN + HIDDEN + t];
        const unsigned long long w0d = pack2(w0, w0);
        const unsigned long long w1d = pack2(w1, w1);
        #pragma unroll
        for (int p = 0; p < RPB / 2; p++) {
            const ulonglong2 xv = *(const ulonglong2*)&xs[p][k];  // 16B smem broadcast
            fma2(acc[p], xv.x, w0d);   // k
            fma2(acc[p], xv.y, w1d);   // k+1
        }
    }

    // ---------------- Epilogue: bias + ReLU -> scratch ----------------
    const float bv = b0[t];
    #pragma unroll
    for (int p = 0; p < RPB / 2; p++) {
        float lo, hi;
        unpack2(acc[p], lo, hi);
        const size_t row = (size_t)row0 + 2 * p;
        g_L0[row * HIDDEN + t]       = fmaxf(lo + bv, 0.f);
        g_L0[(row + 1) * HIDDEN + t] = fmaxf(hi + bv, 0.f);
    }
}

// ============================================================================
// Kernel 2: per root node b:
//   mean_t = ( sum_j 0.5*(neigh_original[b,j,t] - history[neighs1[b,j],t])
//            + sum_i history[h_nodes[b,i],t] ) / 15
//   y = [h1[b] | mean];  out[b] = relu(y @ W1 + b1)
// 1024 blocks x 128 threads; split-K (2 threads per output) for the GEMV.
// ============================================================================
__global__ __launch_bounds__(128)
void final_kernel(const float* __restrict__ history,
                  const float* __restrict__ W1,
                  const float* __restrict__ b1,
                  const int*   __restrict__ neighs1,
                  const int*   __restrict__ h_nodes,
                  float*       __restrict__ out)
{
    __shared__ float ys[2 * HIDDEN];
    __shared__ float part[128];

    const int b = blockIdx.x;
    const int t = threadIdx.x;   // hidden column 0..127

    float s = 0.f;
    #pragma unroll
    for (int j = 0; j < K1; j++) {
        const int n1 = neighs1[b * K1 + j];
        const float no = g_L0[(size_t)(BATCH + b * K1 + j) * HIDDEN + t];
        s += 0.5f * (no - history[(size_t)n1 * HIDDEN + t]);  // * (N_HIST/K1)
    }
    #pragma unroll
    for (int j = 0; j < NHIST; j++) {
        const int hn = h_nodes[b * NHIST + j];
        s += history[(size_t)hn * HIDDEN + t];
    }
    ys[HIDDEN + t] = s * (1.f / (K1 + NHIST));
    ys[t]          = g_L0[(size_t)b * HIDDEN + t];   // h1
    __syncthreads();

    const int o  = t & 63;            // output class
    const int kb = (t >> 6) * HIDDEN; // k-range half
    float a = 0.f;
    #pragma unroll 8
    for (int k = 0; k < HIDDEN; k++)
        a += ys[kb + k] * W1[(size_t)(kb + k) * NCLASS + o];
    part[t] = a;
    __syncthreads();

    if (t < NCLASS)
        out[(size_t)b * NCLASS + t] = fmaxf(part[t] + part[t + 64] + b1[t], 0.f);
}

// ============================================================================
// kernel_launch — graph-capturable, allocation-free.
// Input order per metadata: feats, history, W0, b0, W1, b1, nodes, neighs0,
// neighs1, neighs0_nb, h_nodes. Output: float32 [1024, 64].
// ============================================================================
extern "C" void kernel_launch(void* const* d_in, const int* in_sizes, int n_in,
                              void* d_out, int out_size)
{
    const float* feats      = (const float*)d_in[0];
    const float* history    = (const float*)d_in[1];
    const float* W0         = (const float*)d_in[2];
    const float* b0         = (const float*)d_in[3];
    const float* W1         = (const float*)d_in[4];
    const float* b1         = (const float*)d_in[5];
    const int*   nodes      = (const int*)d_in[6];
    const int*   neighs0    = (const int*)d_in[7];
    const int*   neighs1    = (const int*)d_in[8];
    const int*   neighs0_nb = (const int*)d_in[9];
    const int*   h_nodes    = (const int*)d_in[10];
    float* out = (float*)d_out;

    layer0_kernel<<<NBLK, 128>>>(feats, W0, b0, nodes, neighs0, neighs1, neighs0_nb);
    final_kernel<<<BATCH, 128>>>(history, W1, b1, neighs1, h_nodes, out);
}